// round 4
// baseline (speedup 1.0000x reference)
#include <cuda_runtime.h>
#include <math.h>

// ---------------------------------------------------------------------------
// HistogramLoss on GB300.
//
// feature: [1, 64, 128, 128] fp32 ; label: [1, 1, 512, 512] int32 ; out: scalar fp32
//
// Math:  per class c, dim d:
//   miu = Σ w x / n,  var = Σ w x²/n - miu² + 1e-10,  u = (x-miu)/std
//   S[k] = Σ_q w[c,q] exp(-12.5 (k-u_q)²)   (k = -3..3)
//   hist = S/ΣS, targ = const normalized gaussian, loss = mean smooth_l1
// KDE evaluated via a 2048-bin weighted histogram of u in [-4,4] (δ=1/256)
// convolved with a fixed 666-tap kernel table (bin centers sit on a fixed
// half-offset grid relative to integer k, so one table serves everything).
// ---------------------------------------------------------------------------

#define NUM_C    19
#define PC       16384          // 128*128 coarse pixels
#define DD       64
#define NB       2048           // histogram bins over u in [-4, 4]
#define MTAPS    333            // half window: 333/256 = 1.30 sigma-units*... exp(-12.5*1.3^2)=7e-10
#define GLEN     (2*MTAPS)      // 666

__device__ float  g_w[NUM_C * PC];        // per-class per-coarse-pixel fine-pixel counts (as float)
__device__ int    g_n[NUM_C];             // per-class total fine-pixel counts
__device__ float2 g_param[NUM_C * DD];    // (inv_std, -miu*inv_std)
__device__ float  g_partial[NUM_C * DD];  // per-(c,d) smooth-l1 sum over 7 bins
__device__ float  g_G[GLEN];              // gaussian taps
__device__ float  g_targ[7];              // normalized target histogram

// ---------------------------------------------------------------- init ----
__global__ void k_init() {
    int t = threadIdx.x;
    if (t < NUM_C) g_n[t] = 0;
    for (int i = t; i < GLEN; i += blockDim.x) {
        float z = (332.5f - (float)i) * (1.0f / 256.0f);
        g_G[i] = expf(-12.5f * z * z);
    }
    if (t == 0) {
        float tv[7]; float s = 0.f;
        #pragma unroll
        for (int k = 0; k < 7; k++) { float kk = (float)(k - 3); tv[k] = expf(-0.5f * kk * kk); s += tv[k]; }
        #pragma unroll
        for (int k = 0; k < 7; k++) g_targ[k] = tv[k] / s;
    }
}

// -------------------------------------------------------------- counts ----
// One thread per coarse pixel: count labels in its 4x4 fine block.
__global__ __launch_bounds__(256) void k_counts(const int* __restrict__ label) {
    __shared__ int sn[NUM_C];
    int t = threadIdx.x;
    if (t < NUM_C) sn[t] = 0;
    __syncthreads();

    int q = blockIdx.x * 256 + t;           // 64 blocks * 256 = 16384
    int y = q >> 7, x = q & 127;
    const int4* lp = (const int4*)label;    // 512 ints per fine row = 128 int4
    int base = y * 512 + x;                 // int4 index of fine row 4y, col 4x

    int w[NUM_C];
    #pragma unroll
    for (int c = 0; c < NUM_C; c++) w[c] = 0;

    #pragma unroll
    for (int r = 0; r < 4; r++) {
        int4 v = lp[base + r * 128];
        #pragma unroll
        for (int c = 0; c < NUM_C; c++)
            w[c] += (v.x == c) + (v.y == c) + (v.z == c) + (v.w == c);
    }

    #pragma unroll
    for (int c = 0; c < NUM_C; c++) {
        g_w[c * PC + q] = (float)w[c];
        atomicAdd(&sn[c], w[c]);
    }
    __syncthreads();
    if (t < NUM_C) atomicAdd(&g_n[t], sn[t]);
}

// --------------------------------------------------------------- stats ----
// One block per (d, c): weighted sum and sum-of-squares over 16384 pixels.
__global__ __launch_bounds__(256) void k_stats(const float* __restrict__ feat) {
    int d = blockIdx.x, c = blockIdx.y;
    int t = threadIdx.x;
    const float* __restrict__ wrow = g_w + c * PC;
    const float* __restrict__ xrow = feat + d * PC;

    float s1 = 0.f, s2 = 0.f;
    for (int i = t; i < PC; i += 256) {
        float w = wrow[i], x = xrow[i];
        float wx = w * x;
        s1 += wx;
        s2 = fmaf(wx, x, s2);
    }
    #pragma unroll
    for (int o = 16; o; o >>= 1) {
        s1 += __shfl_down_sync(0xffffffffu, s1, o);
        s2 += __shfl_down_sync(0xffffffffu, s2, o);
    }
    __shared__ float r1[8], r2[8];
    int wid = t >> 5, lane = t & 31;
    if (lane == 0) { r1[wid] = s1; r2[wid] = s2; }
    __syncthreads();
    if (t == 0) {
        float a = 0.f, b = 0.f;
        #pragma unroll
        for (int i = 0; i < 8; i++) { a += r1[i]; b += r2[i]; }
        float n  = (float)g_n[c];
        float ns = fmaxf(n, 1.0f);
        float miu = a / ns;
        float var = b / ns - miu * miu + 1e-10f;
        var = fmaxf(var, 1e-10f);
        float inv_std = rsqrtf(var);
        g_param[c * DD + d] = make_float2(inv_std, -miu * inv_std);
    }
}

// ----------------------------------------------------------------- kde ----
// One block per (d, c): weighted histogram of u in shared memory, then
// convolve with the fixed gaussian table to get the 7 KDE values, then
// smooth-l1 against the constant target.
__global__ __launch_bounds__(256) void k_kde(const float* __restrict__ feat) {
    int d = blockIdx.x, c = blockIdx.y;
    int t = threadIdx.x;

    __shared__ float H[NB];
    __shared__ float S7[7];
    for (int i = t; i < NB; i += 256) H[i] = 0.f;
    __syncthreads();

    float2 p = g_param[c * DD + d];
    const float* __restrict__ wrow = g_w + c * PC;
    const float* __restrict__ xrow = feat + d * PC;

    for (int i = t; i < PC; i += 256) {
        float w = wrow[i];
        if (w != 0.f) {
            float u  = fmaf(xrow[i], p.x, p.y);          // (x - miu)/std
            float jf = fmaf(u, 256.f, 1024.f);           // (u+4)*256
            jf = fminf(fmaxf(jf, 0.f), 2047.f);
            atomicAdd(&H[(int)jf], w);                   // integer-valued adds: exact
        }
    }
    __syncthreads();

    int wid = t >> 5, lane = t & 31;
    if (wid < 7) {
        // bin center u_j = -4 + (j+0.5)/256 ; k = wid-3 ; center index 256*(k+4)
        int j0 = 256 * wid + 256 - MTAPS;
        float acc = 0.f;
        for (int i = lane; i < GLEN; i += 32) {
            int j = j0 + i;
            if (j >= 0 && j < NB) acc = fmaf(g_G[i], H[j], acc);
        }
        #pragma unroll
        for (int o = 16; o; o >>= 1) acc += __shfl_down_sync(0xffffffffu, acc, o);
        if (lane == 0) S7[wid] = acc;
    }
    __syncthreads();

    if (t == 0) {
        float tot = 0.f;
        #pragma unroll
        for (int k = 0; k < 7; k++) tot += S7[k];
        float inv = 1.0f / fmaxf(tot, 1e-30f);
        float ls = 0.f;
        #pragma unroll
        for (int k = 0; k < 7; k++) {
            float dlt = S7[k] * inv - g_targ[k];
            float a = fabsf(dlt);
            ls += (a < 1.f) ? 0.5f * a * a : a - 0.5f;
        }
        g_partial[c * DD + d] = ls;
    }
}

// --------------------------------------------------------------- final ----
__global__ void k_final(float* __restrict__ out) {
    int t = threadIdx.x;
    __shared__ float sl[NUM_C], sa[NUM_C];
    if (t < NUM_C) {
        float s = 0.f;
        for (int d = 0; d < DD; d++) s += g_partial[t * DD + d];
        float act = (g_n[t] >= 1000) ? 1.f : 0.f;
        sl[t] = s * (1.0f / 448.0f) * act;   // mean over 64*7 elements, masked
        sa[t] = act;
    }
    __syncthreads();
    if (t == 0) {
        float L = 0.f, A = 0.f;
        #pragma unroll
        for (int cc = 0; cc < NUM_C; cc++) { L += sl[cc]; A += sa[cc]; }
        out[0] = L / A;
    }
}

// -------------------------------------------------------------- launch ----
extern "C" void kernel_launch(void* const* d_in, const int* in_sizes, int n_in,
                              void* d_out, int out_size) {
    const float* feat  = (const float*)d_in[0];
    const int*   label = (const int*)d_in[1];
    // robustness: identify inputs by element count (feature=1048576, label=262144)
    if (n_in >= 2 && in_sizes[0] == 262144) {
        feat  = (const float*)d_in[1];
        label = (const int*)d_in[0];
    }

    k_init<<<1, 256>>>();
    k_counts<<<64, 256>>>(label);
    dim3 g(DD, NUM_C);
    k_stats<<<g, 256>>>(feat);
    k_kde<<<g, 256>>>(feat);
    k_final<<<1, 32>>>((float*)d_out);
}